// round 14
// baseline (speedup 1.0000x reference)
#include <cuda_runtime.h>
#include <cstdint>

// DepthEmissionRaymarcher: B=2,H=192,W=320,P=128,F=8
// R13 = R12 theory with the divergence bug fixed: ALL __shfl_sync broadcasts
// are warp-unconditional (R12 put them inside a group-divergent branch ->
// deadlock). Feature pts 0-3 are loaded speculatively (same 128B DRAM line as
// pts 0-1, zero marginal bytes); pts 4-7 (a genuine 4th line, P~4%) keep
// per-group predicated loads only (LDG/FFMA are divergence-safe).
// 8 rays/warp, 4-lane groups, float2 lanes. Post-saturation probs are exactly
// 0 -> unconditional adds are bit-exact.

static constexpr int P = 128;
static constexpr int F = 8;
static constexpr int WARPS_PER_BLOCK = 8;
static constexpr int THREADS = WARPS_PER_BLOCK * 32;
static constexpr int RAYS_PER_WARP = 8;

__global__ __launch_bounds__(THREADS)
void raymarch_kernel(const float* __restrict__ dens,
                     const float* __restrict__ feat,
                     const float* __restrict__ len,
                     float* __restrict__ depth_out,
                     float* __restrict__ feat_out,
                     int R)
{
    const unsigned FULL = 0xffffffffu;
    const int lane = threadIdx.x & 31;
    const int warp = threadIdx.x >> 5;
    const int g  = lane >> 2;        // ray-group within warp (0..7)
    const int sg = lane & 3;         // sub-lane: covers points 2sg, 2sg+1

    const int warp_ray0 = (blockIdx.x * WARPS_PER_BLOCK + warp) * RAYS_PER_WARP;
    if (warp_ray0 >= R) return;      // warp-uniform exit

    int ray = warp_ray0 + g;
    const bool valid = ray < R;
    if (!valid) ray = R - 1;         // safe addresses; writes predicated

    const float* draw = dens + (size_t)ray * P;
    const float* lraw = len  + (size_t)ray * P;
    const float* fraw = feat + (size_t)ray * P * F;

    float base = 0.0f;               // raw cumsum before current chunk
    float depth = 0.0f;
    float acc0 = 0.0f, acc1 = 0.0f;  // feature accum: indices 2sg, 2sg+1

    #pragma unroll 1
    for (int p0 = 0; p0 < P; p0 += 8) {
        const int pl = p0 + 2 * sg;  // this lane's first point

        // ---- front-batched loads: dens, len, feature pts 0-3.
        // pts 0-3 features = ONE 128B line: speculation is byte-free. ----
        float2 d2 = __ldcs(reinterpret_cast<const float2*>(draw + pl));
        float2 l2 = __ldcs(reinterpret_cast<const float2*>(lraw + pl));
        float2 f0 = __ldcs(reinterpret_cast<const float2*>(fraw + (p0 + 0) * F + 2 * sg));
        float2 f1 = __ldcs(reinterpret_cast<const float2*>(fraw + (p0 + 1) * F + 2 * sg));
        float2 f2 = __ldcs(reinterpret_cast<const float2*>(fraw + (p0 + 2) * F + 2 * sg));
        float2 f3 = __ldcs(reinterpret_cast<const float2*>(fraw + (p0 + 3) * F + 2 * sg));

        if (pl + 1 == P - 1) d2.y = 1.0f;   // wall=True on furthest sample

        // ---- scan: pair-sum then 2-round inclusive scan over 4 lanes ----
        const float s = d2.x + d2.y;
        float inc = s;
        {
            float v = __shfl_up_sync(FULL, inc, 1, 4);
            if (sg >= 1) inc += v;
            v = __shfl_up_sync(FULL, inc, 2, 4);
            if (sg >= 2) inc += v;
        }
        const float b    = base + (inc - s);      // cumsum before this lane's pts
        const float ckm1 = fminf(b, 1.0f);
        const float ck0  = fminf(b + d2.x, 1.0f);
        const float ck1  = fminf(b + s, 1.0f);
        const float pr0  = ck0 - ckm1;            // exactly 0 past saturation
        const float pr1  = ck1 - ck0;

        depth += pr0 * l2.x + pr1 * l2.y;

        // per-group saturation nibble (bit i = group lane i saturated)
        const unsigned mb = __ballot_sync(FULL, ck1 >= 1.0f);
        const unsigned gbits = (mb >> (g * 4)) & 0xFu;

        // ---- ALL prob broadcasts unconditional (warp-converged) ----
        const float pw0 = __shfl_sync(FULL, pr0, 0, 4);
        const float pw1 = __shfl_sync(FULL, pr1, 0, 4);
        const float pw2 = __shfl_sync(FULL, pr0, 1, 4);
        const float pw3 = __shfl_sync(FULL, pr1, 1, 4);
        const float pw4 = __shfl_sync(FULL, pr0, 2, 4);
        const float pw5 = __shfl_sync(FULL, pr1, 2, 4);
        const float pw6 = __shfl_sync(FULL, pr0, 3, 4);
        const float pw7 = __shfl_sync(FULL, pr1, 3, 4);

        // ---- feature pts 0-3: unconditional (probs are 0 when unneeded) ----
        acc0 += pw0 * f0.x + pw1 * f1.x + pw2 * f2.x + pw3 * f3.x;
        acc1 += pw0 * f0.y + pw1 * f1.y + pw2 * f2.y + pw3 * f3.y;

        // ---- pts 4-7: genuine extra 128B line; per-group predicated loads
        // and FMAs only (no sync ops inside the divergent region) ----
        if ((gbits & 3u) == 0u) {
            float2 f4 = __ldcs(reinterpret_cast<const float2*>(fraw + (p0 + 4) * F + 2 * sg));
            float2 f5 = __ldcs(reinterpret_cast<const float2*>(fraw + (p0 + 5) * F + 2 * sg));
            acc0 += pw4 * f4.x + pw5 * f5.x;
            acc1 += pw4 * f4.y + pw5 * f5.y;
            if ((gbits & 7u) == 0u) {
                float2 f6 = __ldcs(reinterpret_cast<const float2*>(fraw + (p0 + 6) * F + 2 * sg));
                float2 f7 = __ldcs(reinterpret_cast<const float2*>(fraw + (p0 + 7) * F + 2 * sg));
                acc0 += pw6 * f6.x + pw7 * f7.x;
                acc1 += pw6 * f6.y + pw7 * f7.y;
            }
        }

        // ---- all groups saturated? (bit 4g+3 = lane3's ck1 = cumsum pt7) ----
        if ((mb & 0x88888888u) == 0x88888888u) break;

        base += __shfl_sync(FULL, inc, 3, 4);  // carry raw cumsum (uniform)
    }

    // ---- depth: reduce over the 4 lanes of the group ----
    depth += __shfl_xor_sync(FULL, depth, 1);
    depth += __shfl_xor_sync(FULL, depth, 2);
    if (valid && sg == 0) depth_out[ray] = depth;

    // ---- features: lane stores feats {2sg, 2sg+1}; fully coalesced ----
    if (valid)
        *reinterpret_cast<float2*>(feat_out + (size_t)ray * F + 2 * sg) =
            make_float2(acc0, acc1);
}

extern "C" void kernel_launch(void* const* d_in, const int* in_sizes, int n_in,
                              void* d_out, int out_size)
{
    const float* dens = (const float*)d_in[0];  // (B,H,W,P,1)
    const float* feat = (const float*)d_in[1];  // (B,H,W,P,F)
    const float* len  = (const float*)d_in[2];  // (B,H,W,P)

    const int R = in_sizes[2] / P;              // number of rays

    float* depth_out = (float*)d_out;           // (B,H,W) flattened
    float* feat_out  = depth_out + R;           // (B,H,W,F) flattened

    const int rays_per_block = WARPS_PER_BLOCK * RAYS_PER_WARP;
    const int blocks = (R + rays_per_block - 1) / rays_per_block;
    raymarch_kernel<<<blocks, THREADS>>>(dens, feat, len, depth_out, feat_out, R);
}